// round 2
// baseline (speedup 1.0000x reference)
#include <cuda_runtime.h>
#include <math.h>

#define B_SZ 16384
#define D_SZ 4096
#define H_SZ 128
#define E_SZ 64
#define K_TOP 8

// scratch for hidden activations (B x H) = 8 MB
__device__ float g_h[B_SZ * H_SZ];

// ---------------------------------------------------------------------------
// Kernel 1: h = silu(features @ W1 + b1)
// features = [r_pooled | step | hidden_norm | confidence]  (B x 4099)
// GEMM M=16384, N=128, K=4096 plus 3 rank-1 terms folded into the epilogue.
// BM=64, BN=128, BK=16, 128 threads, 8x8 microtile per thread.
// ---------------------------------------------------------------------------
__global__ __launch_bounds__(128)
void gemm1_kernel(const float* __restrict__ A,     // (B, D)
                  const float* __restrict__ W1,    // (D+3, H)
                  const float* __restrict__ b1,    // (H)
                  const float* __restrict__ stepp, // (1)
                  const float* __restrict__ hn,    // (B)
                  const float* __restrict__ conf)  // (B)
{
    __shared__ float As[16][64];    // transposed: As[k][m]
    __shared__ float Bs[16][128];   // Bs[k][n]

    const int tid = threadIdx.x;
    const int tx = tid & 15;        // n-dir: 16 thread cols
    const int ty = tid >> 4;        // m-dir: 8 thread rows
    const int m0 = blockIdx.x * 64;

    float acc[8][8];
#pragma unroll
    for (int i = 0; i < 8; ++i)
#pragma unroll
        for (int j = 0; j < 8; ++j) acc[i][j] = 0.0f;

    for (int k0 = 0; k0 < D_SZ; k0 += 16) {
        // --- load A tile (64 rows x 16 k) : 256 float4, 2 per thread ---
#pragma unroll
        for (int j = 0; j < 2; ++j) {
            int i = tid * 2 + j;
            int row = i >> 2;           // 0..63
            int k4  = i & 3;            // 0..3
            float4 a4 = *(const float4*)&A[(size_t)(m0 + row) * D_SZ + k0 + k4 * 4];
            As[k4 * 4 + 0][row] = a4.x;
            As[k4 * 4 + 1][row] = a4.y;
            As[k4 * 4 + 2][row] = a4.z;
            As[k4 * 4 + 3][row] = a4.w;
        }
        // --- load B tile (16 k x 128 n) : 512 float4, 4 per thread ---
#pragma unroll
        for (int t = 0; t < 4; ++t) {
            int i = tid + t * 128;
            int row = i >> 5;           // 0..15
            int c4  = i & 31;           // 0..31
            *(float4*)&Bs[row][c4 * 4] =
                *(const float4*)&W1[(size_t)(k0 + row) * H_SZ + c4 * 4];
        }
        __syncthreads();

#pragma unroll
        for (int kk = 0; kk < 16; ++kk) {
            float a[8], b[8];
            *(float4*)&a[0] = *(const float4*)&As[kk][ty * 8];
            *(float4*)&a[4] = *(const float4*)&As[kk][ty * 8 + 4];
            *(float4*)&b[0] = *(const float4*)&Bs[kk][tx * 8];
            *(float4*)&b[4] = *(const float4*)&Bs[kk][tx * 8 + 4];
#pragma unroll
            for (int i = 0; i < 8; ++i)
#pragma unroll
                for (int j = 0; j < 8; ++j)
                    acc[i][j] = fmaf(a[i], b[j], acc[i][j]);
        }
        __syncthreads();
    }

    // --- epilogue: extra feature columns (rank-1 terms), bias, silu ---
    const float step = stepp[0];
    float colc[8], w2r[8], w3r[8];
#pragma unroll
    for (int j = 0; j < 8; ++j) {
        int col = tx * 8 + j;
        colc[j] = fmaf(step, W1[(size_t)D_SZ * H_SZ + col], b1[col]);
        w2r[j]  = W1[(size_t)(D_SZ + 1) * H_SZ + col];
        w3r[j]  = W1[(size_t)(D_SZ + 2) * H_SZ + col];
    }
#pragma unroll
    for (int i = 0; i < 8; ++i) {
        int row = m0 + ty * 8 + i;
        float hv = hn[row];
        float cv = conf[row];
#pragma unroll
        for (int j = 0; j < 8; ++j) {
            float x = acc[i][j] + colc[j] + hv * w2r[j] + cv * w3r[j];
            // silu(x) = x * sigmoid(x)
            float s = x / (1.0f + expf(-x));
            g_h[(size_t)row * H_SZ + tx * 8 + j] = s;
        }
    }
}

// ---------------------------------------------------------------------------
// Kernel 2: logits = h @ W2 + b2; top-8 per row; softmax; scatter.
// One warp per row. Lane l owns logits l and l+32.
// Output layout: d_out[0 : B*E) = weights, d_out[B*E : 2*B*E) = logits.
// ---------------------------------------------------------------------------
__global__ __launch_bounds__(256)
void router_kernel(const float* __restrict__ W2,  // (H, E) row-major
                   const float* __restrict__ b2,  // (E)
                   float* __restrict__ out)
{
    __shared__ float Ws[H_SZ * E_SZ];   // 32 KB
    __shared__ float b2s[E_SZ];

    const int tid = threadIdx.x;
    for (int i = tid; i < H_SZ * E_SZ; i += 256) Ws[i] = W2[i];
    if (tid < E_SZ) b2s[tid] = b2[tid];
    __syncthreads();

    const int lane = tid & 31;
    const int warp = tid >> 5;
    const int r = blockIdx.x * 8 + warp;

    // stage h row into registers (coalesced), broadcast via shfl
    float hreg[4];
#pragma unroll
    for (int q = 0; q < 4; ++q)
        hreg[q] = g_h[(size_t)r * H_SZ + q * 32 + lane];

    float acc0 = b2s[lane];
    float acc1 = b2s[lane + 32];
#pragma unroll
    for (int k = 0; k < H_SZ; ++k) {
        float hv = __shfl_sync(0xffffffffu, hreg[k >> 5], k & 31);
        acc0 = fmaf(hv, Ws[k * E_SZ + lane], acc0);
        acc1 = fmaf(hv, Ws[k * E_SZ + lane + 32], acc1);
    }

    float* out_w = out;
    float* out_l = out + (size_t)B_SZ * E_SZ;
    out_l[(size_t)r * E_SZ + lane]      = acc0;
    out_l[(size_t)r * E_SZ + lane + 32] = acc1;

    // --- warp top-8 (value desc, ties -> lower index, matching lax.top_k) ---
    bool used0 = false, used1 = false;
    float tv[K_TOP];
    int   ti[K_TOP];
#pragma unroll
    for (int t = 0; t < K_TOP; ++t) {
        float mv = -3.402823466e38f;
        int   mi = 1 << 30;
        if (!used0) { mv = acc0; mi = lane; }
        if (!used1 && (acc1 > mv || (acc1 == mv && lane + 32 < mi))) {
            mv = acc1; mi = lane + 32;
        }
#pragma unroll
        for (int off = 16; off > 0; off >>= 1) {
            float ov = __shfl_xor_sync(0xffffffffu, mv, off);
            int   oi = __shfl_xor_sync(0xffffffffu, mi, off);
            if (ov > mv || (ov == mv && oi < mi)) { mv = ov; mi = oi; }
        }
        tv[t] = mv;   // all lanes agree
        ti[t] = mi;
        if (mi == lane)      used0 = true;
        if (mi == lane + 32) used1 = true;
    }

    // --- softmax over top-8 (tv[0] is the max) ---
    float mx = tv[0];
    float s = 0.0f;
    float ev[K_TOP];
#pragma unroll
    for (int t = 0; t < K_TOP; ++t) { ev[t] = expf(tv[t] - mx); s += ev[t]; }
    float inv = 1.0f / s;

    float w0 = 0.0f, w1 = 0.0f;
#pragma unroll
    for (int t = 0; t < K_TOP; ++t) {
        float e = ev[t] * inv;
        if (ti[t] == lane)      w0 = e;
        if (ti[t] == lane + 32) w1 = e;
    }
    out_w[(size_t)r * E_SZ + lane]      = w0;
    out_w[(size_t)r * E_SZ + lane + 32] = w1;
}

// ---------------------------------------------------------------------------
extern "C" void kernel_launch(void* const* d_in, const int* in_sizes, int n_in,
                              void* d_out, int out_size) {
    const float* r_pooled    = (const float*)d_in[0];
    const float* step_frac   = (const float*)d_in[1];
    const float* hidden_norm = (const float*)d_in[2];
    const float* confidence  = (const float*)d_in[3];
    const float* W1          = (const float*)d_in[4];
    const float* b1          = (const float*)d_in[5];
    const float* W2          = (const float*)d_in[6];
    const float* b2          = (const float*)d_in[7];
    float* out = (float*)d_out;

    gemm1_kernel<<<B_SZ / 64, 128>>>(r_pooled, W1, b1, step_frac,
                                     hidden_norm, confidence);
    router_kernel<<<B_SZ / 8, 256>>>(W2, b2, out);
}

// round 6
// speedup vs baseline: 1.4433x; 1.4433x over previous
#include <cuda_runtime.h>
#include <math.h>
#include <stdint.h>

#define B_SZ 16384
#define D_SZ 4096
#define H_SZ 128
#define E_SZ 64
#define K_TOP 8

// scratch for hidden activations (B x H) = 8 MB
__device__ float g_h[B_SZ * H_SZ];

__device__ __forceinline__ uint32_t f2tf32(float x) {
    uint32_t r;
    asm("cvt.rna.tf32.f32 %0, %1;" : "=r"(r) : "f"(x));
    return r;
}

__device__ __forceinline__ void split_tf32(float x, uint32_t& hi, uint32_t& lo) {
    hi = f2tf32(x);
    lo = f2tf32(x - __uint_as_float(hi));
}

#define MMA_TF32(C, A0, A1, A2, A3, B0, B1)                                   \
    asm volatile(                                                             \
        "mma.sync.aligned.m16n8k8.row.col.f32.tf32.tf32.f32 "                 \
        "{%0,%1,%2,%3}, {%4,%5,%6,%7}, {%8,%9}, {%0,%1,%2,%3};"               \
        : "+f"(C[0]), "+f"(C[1]), "+f"(C[2]), "+f"(C[3])                      \
        : "r"(A0), "r"(A1), "r"(A2), "r"(A3), "r"(B0), "r"(B1))

// ---------------------------------------------------------------------------
// Kernel 1: h = silu(features @ W1 + b1), 3xTF32 with segmented accumulation.
// BM=128, BN=128, BK=16. 512 threads = 16 warps (4m x 4n), warp tile 32x32.
// Every 4 k-chunks the RZ-accumulated MMA partials are drained into RN fp32
// sums to suppress tensor-core round-toward-zero bias.
// ---------------------------------------------------------------------------
#define BK 16
#define AS_STRIDE 20   // banks (20g+tg)%32 all distinct
#define BS_STRIDE 136  // banks (8tg+g)%32 all distinct

__global__ __launch_bounds__(512)
void gemm1_3xtf32_kernel(const float* __restrict__ A,     // (B, D)
                         const float* __restrict__ W1,    // (D+3, H)
                         const float* __restrict__ b1,    // (H)
                         const float* __restrict__ stepp, // (1)
                         const float* __restrict__ hn,    // (B)
                         const float* __restrict__ conf)  // (B)
{
    __shared__ uint32_t AsH[128 * AS_STRIDE];
    __shared__ uint32_t AsL[128 * AS_STRIDE];
    __shared__ uint32_t BsH[BK * BS_STRIDE];
    __shared__ uint32_t BsL[BK * BS_STRIDE];

    const int tid  = threadIdx.x;
    const int lane = tid & 31;
    const int w    = tid >> 5;
    const int wm   = (w & 3) * 32;   // warp m-offset (4 warps in m)
    const int wn   = (w >> 2) * 32;  // warp n-offset (4 warps in n)
    const int g    = lane >> 2;      // 0..7
    const int tg   = lane & 3;       // 0..3
    const int m0   = blockIdx.x * 128;

    float acc[2][4][4];   // RZ-side MMA accumulators (reset each segment)
    float sum[2][4][4];   // RN-side running sums
#pragma unroll
    for (int mi = 0; mi < 2; ++mi)
#pragma unroll
        for (int ni = 0; ni < 4; ++ni)
#pragma unroll
            for (int c = 0; c < 4; ++c) { acc[mi][ni][c] = 0.0f; sum[mi][ni][c] = 0.0f; }

    // One float4 of A and one of B per thread per iteration.
    const int arow = tid >> 2;          // 0..127
    const int ak   = (tid & 3) * 4;     // 0,4,8,12
    const int brow = tid >> 5;          // 0..15
    const int bc   = (tid & 31) * 4;    // 0..124

    float4 pa = *(const float4*)&A[(size_t)(m0 + arow) * D_SZ + ak];
    float4 pb = *(const float4*)&W1[(size_t)brow * H_SZ + bc];

    for (int it = 0; it < D_SZ / BK; ++it) {
        __syncthreads();
        {
            uint4 h4, l4;
            split_tf32(pa.x, h4.x, l4.x); split_tf32(pa.y, h4.y, l4.y);
            split_tf32(pa.z, h4.z, l4.z); split_tf32(pa.w, h4.w, l4.w);
            int ao = arow * AS_STRIDE + ak;
            *(uint4*)&AsH[ao] = h4;
            *(uint4*)&AsL[ao] = l4;
            split_tf32(pb.x, h4.x, l4.x); split_tf32(pb.y, h4.y, l4.y);
            split_tf32(pb.z, h4.z, l4.z); split_tf32(pb.w, h4.w, l4.w);
            int bo = brow * BS_STRIDE + bc;
            *(uint4*)&BsH[bo] = h4;
            *(uint4*)&BsL[bo] = l4;
        }
        __syncthreads();

        if (it + 1 < D_SZ / BK) {
            int k0 = (it + 1) * BK;
            pa = *(const float4*)&A[(size_t)(m0 + arow) * D_SZ + k0 + ak];
            pb = *(const float4*)&W1[(size_t)(k0 + brow) * H_SZ + bc];
        }

#pragma unroll
        for (int ks = 0; ks < 2; ++ks) {
            uint32_t aH[2][4], aL[2][4], bH[4][2], bL[4][2];
#pragma unroll
            for (int mi = 0; mi < 2; ++mi) {
                int base = (wm + mi * 16 + g) * AS_STRIDE + ks * 8 + tg;
                aH[mi][0] = AsH[base];
                aH[mi][1] = AsH[base + 8 * AS_STRIDE];
                aH[mi][2] = AsH[base + 4];
                aH[mi][3] = AsH[base + 8 * AS_STRIDE + 4];
                aL[mi][0] = AsL[base];
                aL[mi][1] = AsL[base + 8 * AS_STRIDE];
                aL[mi][2] = AsL[base + 4];
                aL[mi][3] = AsL[base + 8 * AS_STRIDE + 4];
            }
#pragma unroll
            for (int ni = 0; ni < 4; ++ni) {
                int base = (ks * 8 + tg) * BS_STRIDE + wn + ni * 8 + g;
                bH[ni][0] = BsH[base];
                bH[ni][1] = BsH[base + 4 * BS_STRIDE];
                bL[ni][0] = BsL[base];
                bL[ni][1] = BsL[base + 4 * BS_STRIDE];
            }
#pragma unroll
            for (int mi = 0; mi < 2; ++mi)
#pragma unroll
                for (int ni = 0; ni < 4; ++ni) {
                    float* c = acc[mi][ni];
                    MMA_TF32(c, aL[mi][0], aL[mi][1], aL[mi][2], aL[mi][3],
                             bH[ni][0], bH[ni][1]);
                    MMA_TF32(c, aH[mi][0], aH[mi][1], aH[mi][2], aH[mi][3],
                             bL[ni][0], bL[ni][1]);
                    MMA_TF32(c, aH[mi][0], aH[mi][1], aH[mi][2], aH[mi][3],
                             bH[ni][0], bH[ni][1]);
                }
        }

        // drain RZ accumulators into RN sums every 4 chunks (k = 64)
        if ((it & 3) == 3) {
#pragma unroll
            for (int mi = 0; mi < 2; ++mi)
#pragma unroll
                for (int ni = 0; ni < 4; ++ni)
#pragma unroll
                    for (int c = 0; c < 4; ++c) {
                        sum[mi][ni][c] += acc[mi][ni][c];
                        acc[mi][ni][c] = 0.0f;
                    }
        }
    }

    // --- epilogue: extra feature cols (rank-1), bias, silu, store g_h ---
    const float step = stepp[0];
    float colc[4][2], w2r[4][2], w3r[4][2];
#pragma unroll
    for (int ni = 0; ni < 4; ++ni)
#pragma unroll
        for (int j = 0; j < 2; ++j) {
            int col = wn + ni * 8 + 2 * tg + j;
            colc[ni][j] = fmaf(step, W1[(size_t)D_SZ * H_SZ + col], b1[col]);
            w2r[ni][j]  = W1[(size_t)(D_SZ + 1) * H_SZ + col];
            w3r[ni][j]  = W1[(size_t)(D_SZ + 2) * H_SZ + col];
        }
#pragma unroll
    for (int mi = 0; mi < 2; ++mi) {
        int r0 = m0 + wm + mi * 16 + g;
        int r1 = r0 + 8;
        float hv0 = hn[r0], cv0 = conf[r0];
        float hv1 = hn[r1], cv1 = conf[r1];
#pragma unroll
        for (int ni = 0; ni < 4; ++ni) {
            int col0 = wn + ni * 8 + 2 * tg;
            float x00 = sum[mi][ni][0] + colc[ni][0] + hv0 * w2r[ni][0] + cv0 * w3r[ni][0];
            float x01 = sum[mi][ni][1] + colc[ni][1] + hv0 * w2r[ni][1] + cv0 * w3r[ni][1];
            float x10 = sum[mi][ni][2] + colc[ni][0] + hv1 * w2r[ni][0] + cv1 * w3r[ni][0];
            float x11 = sum[mi][ni][3] + colc[ni][1] + hv1 * w2r[ni][1] + cv1 * w3r[ni][1];
            float2 s0, s1;
            s0.x = x00 / (1.0f + expf(-x00));
            s0.y = x01 / (1.0f + expf(-x01));
            s1.x = x10 / (1.0f + expf(-x10));
            s1.y = x11 / (1.0f + expf(-x11));
            *(float2*)&g_h[(size_t)r0 * H_SZ + col0] = s0;
            *(float2*)&g_h[(size_t)r1 * H_SZ + col0] = s1;
        }
    }
}

// ---------------------------------------------------------------------------
// Kernel 2: logits = h @ W2 + b2; top-8 per row; softmax; scatter.
// One warp per row (unchanged — passed in round 2).
// ---------------------------------------------------------------------------
__global__ __launch_bounds__(256)
void router_kernel(const float* __restrict__ W2,  // (H, E) row-major
                   const float* __restrict__ b2,  // (E)
                   float* __restrict__ out)
{
    __shared__ float Ws[H_SZ * E_SZ];   // 32 KB
    __shared__ float b2s[E_SZ];

    const int tid = threadIdx.x;
    for (int i = tid; i < H_SZ * E_SZ; i += 256) Ws[i] = W2[i];
    if (tid < E_SZ) b2s[tid] = b2[tid];
    __syncthreads();

    const int lane = tid & 31;
    const int warp = tid >> 5;
    const int r = blockIdx.x * 8 + warp;

    float hreg[4];
#pragma unroll
    for (int q = 0; q < 4; ++q)
        hreg[q] = g_h[(size_t)r * H_SZ + q * 32 + lane];

    float acc0 = b2s[lane];
    float acc1 = b2s[lane + 32];
#pragma unroll
    for (int k = 0; k < H_SZ; ++k) {
        float hv = __shfl_sync(0xffffffffu, hreg[k >> 5], k & 31);
        acc0 = fmaf(hv, Ws[k * E_SZ + lane], acc0);
        acc1 = fmaf(hv, Ws[k * E_SZ + lane + 32], acc1);
    }

    float* out_w = out;
    float* out_l = out + (size_t)B_SZ * E_SZ;
    out_l[(size_t)r * E_SZ + lane]      = acc0;
    out_l[(size_t)r * E_SZ + lane + 32] = acc1;

    bool used0 = false, used1 = false;
    float tv[K_TOP];
    int   ti[K_TOP];
#pragma unroll
    for (int t = 0; t < K_TOP; ++t) {
        float mv = -3.402823466e38f;
        int   mi = 1 << 30;
        if (!used0) { mv = acc0; mi = lane; }
        if (!used1 && (acc1 > mv || (acc1 == mv && lane + 32 < mi))) {
            mv = acc1; mi = lane + 32;
        }
#pragma unroll
        for (int off = 16; off > 0; off >>= 1) {
            float ov = __shfl_xor_sync(0xffffffffu, mv, off);
            int   oi = __shfl_xor_sync(0xffffffffu, mi, off);
            if (ov > mv || (ov == mv && oi < mi)) { mv = ov; mi = oi; }
        }
        tv[t] = mv;
        ti[t] = mi;
        if (mi == lane)      used0 = true;
        if (mi == lane + 32) used1 = true;
    }

    float mx = tv[0];
    float s = 0.0f;
    float ev[K_TOP];
#pragma unroll
    for (int t = 0; t < K_TOP; ++t) { ev[t] = expf(tv[t] - mx); s += ev[t]; }
    float inv = 1.0f / s;

    float w0 = 0.0f, w1 = 0.0f;
#pragma unroll
    for (int t = 0; t < K_TOP; ++t) {
        float e = ev[t] * inv;
        if (ti[t] == lane)      w0 = e;
        if (ti[t] == lane + 32) w1 = e;
    }
    out_w[(size_t)r * E_SZ + lane]      = w0;
    out_w[(size_t)r * E_SZ + lane + 32] = w1;
}

// ---------------------------------------------------------------------------
extern "C" void kernel_launch(void* const* d_in, const int* in_sizes, int n_in,
                              void* d_out, int out_size) {
    const float* r_pooled    = (const float*)d_in[0];
    const float* step_frac   = (const float*)d_in[1];
    const float* hidden_norm = (const float*)d_in[2];
    const float* confidence  = (const float*)d_in[3];
    const float* W1          = (const float*)d_in[4];
    const float* b1          = (const float*)d_in[5];
    const float* W2          = (const float*)d_in[6];
    const float* b2          = (const float*)d_in[7];
    float* out = (float*)d_out;

    gemm1_3xtf32_kernel<<<B_SZ / 128, 512>>>(r_pooled, W1, b1, step_frac,
                                             hidden_norm, confidence);
    router_kernel<<<B_SZ / 8, 256>>>(W2, b2, out);
}

// round 8
// speedup vs baseline: 1.6871x; 1.1690x over previous
#include <cuda_runtime.h>
#include <math.h>
#include <stdint.h>

#define B_SZ 16384
#define D_SZ 4096
#define H_SZ 128
#define E_SZ 64
#define K_TOP 8

// scratch for hidden activations (B x H) = 8 MB
__device__ float g_h[B_SZ * H_SZ];

__device__ __forceinline__ uint32_t f2tf32(float x) {
    uint32_t r;
    asm("cvt.rna.tf32.f32 %0, %1;" : "=r"(r) : "f"(x));
    return r;
}
__device__ __forceinline__ void split_tf32(float x, uint32_t& hi, uint32_t& lo) {
    hi = f2tf32(x);
    lo = f2tf32(x - __uint_as_float(hi));
}

#define MMA_TF32(C, A0, A1, A2, A3, B0, B1)                                   \
    asm volatile(                                                             \
        "mma.sync.aligned.m16n8k8.row.col.f32.tf32.tf32.f32 "                 \
        "{%0,%1,%2,%3}, {%4,%5,%6,%7}, {%8,%9}, {%0,%1,%2,%3};"               \
        : "+f"(C[0]), "+f"(C[1]), "+f"(C[2]), "+f"(C[3])                      \
        : "r"(A0), "r"(A1), "r"(A2), "r"(A3), "r"(B0), "r"(B1))

// ---------------------------------------------------------------------------
// Kernel 1: h = silu(features @ W1 + b1), 3xTF32 mma.sync, double-buffered.
// BM=128, BN=128, BK=32. 512 threads = 16 warps (4m x 4n), warp tile 32x32.
// 2-stage smem pipeline, ONE __syncthreads per k-iteration.
// RZ-accumulated MMA partials drained into RN fp32 sums every 64 k.
// ---------------------------------------------------------------------------
#define BK 32
#define AS_STRIDE 36   // bank(4r + 8ks + tg): frag loads conflict-free
#define BS_STRIDE 136  // bank(8tg + g): frag loads conflict-free

// u32-element sizes / offsets within dynamic smem
#define A_STG   (128 * AS_STRIDE)        // 4608 u32
#define B_STG   (BK * BS_STRIDE)         // 4352 u32
#define STG     (2 * A_STG + 2 * B_STG)  // 17920 u32 per stage
#define OFF_AH(s) ((s) * STG + 0)
#define OFF_AL(s) ((s) * STG + A_STG)
#define OFF_BH(s) ((s) * STG + 2 * A_STG)
#define OFF_BL(s) ((s) * STG + 2 * A_STG + B_STG)
#define SMEM_U32  (2 * STG)              // 35840 u32 = 143360 bytes

__global__ __launch_bounds__(512)
void gemm1_3xtf32_kernel(const float* __restrict__ A,     // (B, D)
                         const float* __restrict__ W1,    // (D+3, H)
                         const float* __restrict__ b1,    // (H)
                         const float* __restrict__ stepp, // (1)
                         const float* __restrict__ hn,    // (B)
                         const float* __restrict__ conf)  // (B)
{
    extern __shared__ uint32_t smem[];

    const int tid  = threadIdx.x;
    const int lane = tid & 31;
    const int w    = tid >> 5;
    const int wm   = (w & 3) * 32;   // warp m-offset (4 warps in m)
    const int wn   = (w >> 2) * 32;  // warp n-offset (4 warps in n)
    const int g    = lane >> 2;      // 0..7
    const int tg   = lane & 3;       // 0..3
    const int m0   = blockIdx.x * 128;

    float acc[2][4][4];   // RZ-side MMA accumulators (reset each segment)
    float sum[2][4][4];   // RN-side running sums
#pragma unroll
    for (int mi = 0; mi < 2; ++mi)
#pragma unroll
        for (int ni = 0; ni < 4; ++ni)
#pragma unroll
            for (int c = 0; c < 4; ++c) { acc[mi][ni][c] = 0.0f; sum[mi][ni][c] = 0.0f; }

    // Writer mapping (per iteration, 2 float4 of A + 2 of B per thread):
    // A tile 128x32 = 1024 float4: f = i*512+tid, arow=f>>3, ak=(f&7)*4
    // B tile  32x128 = 1024 float4: f = i*512+tid, brow=f>>5, bc=(f&31)*4
    float4 pa[2], pb[2];
#pragma unroll
    for (int i = 0; i < 2; ++i) {
        int f = i * 512 + tid;
        pa[i] = *(const float4*)&A[(size_t)(m0 + (f >> 3)) * D_SZ + (f & 7) * 4];
        pb[i] = *(const float4*)&W1[(size_t)(f >> 5) * H_SZ + (f & 31) * 4];
    }

    // prologue: fill stage 0
#pragma unroll
    for (int i = 0; i < 2; ++i) {
        int f = i * 512 + tid;
        uint4 h4, l4;
        split_tf32(pa[i].x, h4.x, l4.x); split_tf32(pa[i].y, h4.y, l4.y);
        split_tf32(pa[i].z, h4.z, l4.z); split_tf32(pa[i].w, h4.w, l4.w);
        int ao = (f >> 3) * AS_STRIDE + (f & 7) * 4;
        *(uint4*)&smem[OFF_AH(0) + ao] = h4;
        *(uint4*)&smem[OFF_AL(0) + ao] = l4;
        split_tf32(pb[i].x, h4.x, l4.x); split_tf32(pb[i].y, h4.y, l4.y);
        split_tf32(pb[i].z, h4.z, l4.z); split_tf32(pb[i].w, h4.w, l4.w);
        int bo = (f >> 5) * BS_STRIDE + (f & 31) * 4;
        *(uint4*)&smem[OFF_BH(0) + bo] = h4;
        *(uint4*)&smem[OFF_BL(0) + bo] = l4;
    }

    const int NIT = D_SZ / BK;   // 128
    for (int it = 0; it < NIT; ++it) {
        __syncthreads();   // stores of tile 'it' visible; reads of it-1 complete
        const int cur = it & 1;
        const bool pre = (it + 1 < NIT);

        if (pre) {
            int k0 = (it + 1) * BK;
#pragma unroll
            for (int i = 0; i < 2; ++i) {
                int f = i * 512 + tid;
                pa[i] = *(const float4*)&A[(size_t)(m0 + (f >> 3)) * D_SZ + k0 + (f & 7) * 4];
                pb[i] = *(const float4*)&W1[(size_t)(k0 + (f >> 5)) * H_SZ + (f & 31) * 4];
            }
        }

        const uint32_t* AsH = &smem[OFF_AH(cur)];
        const uint32_t* AsL = &smem[OFF_AL(cur)];
        const uint32_t* BsH = &smem[OFF_BH(cur)];
        const uint32_t* BsL = &smem[OFF_BL(cur)];

#pragma unroll
        for (int ks = 0; ks < 4; ++ks) {
            uint32_t aH[2][4], aL[2][4], bH[4][2], bL[4][2];
#pragma unroll
            for (int mi = 0; mi < 2; ++mi) {
                int base = (wm + mi * 16 + g) * AS_STRIDE + ks * 8 + tg;
                aH[mi][0] = AsH[base];
                aH[mi][1] = AsH[base + 8 * AS_STRIDE];
                aH[mi][2] = AsH[base + 4];
                aH[mi][3] = AsH[base + 8 * AS_STRIDE + 4];
                aL[mi][0] = AsL[base];
                aL[mi][1] = AsL[base + 8 * AS_STRIDE];
                aL[mi][2] = AsL[base + 4];
                aL[mi][3] = AsL[base + 8 * AS_STRIDE + 4];
            }
#pragma unroll
            for (int ni = 0; ni < 4; ++ni) {
                int base = (ks * 8 + tg) * BS_STRIDE + wn + ni * 8 + g;
                bH[ni][0] = BsH[base];
                bH[ni][1] = BsH[base + 4 * BS_STRIDE];
                bL[ni][0] = BsL[base];
                bL[ni][1] = BsL[base + 4 * BS_STRIDE];
            }
#pragma unroll
            for (int mi = 0; mi < 2; ++mi)
#pragma unroll
                for (int ni = 0; ni < 4; ++ni) {
                    float* c = acc[mi][ni];
                    MMA_TF32(c, aL[mi][0], aL[mi][1], aL[mi][2], aL[mi][3],
                             bH[ni][0], bH[ni][1]);
                    MMA_TF32(c, aH[mi][0], aH[mi][1], aH[mi][2], aH[mi][3],
                             bL[ni][0], bL[ni][1]);
                    MMA_TF32(c, aH[mi][0], aH[mi][1], aH[mi][2], aH[mi][3],
                             bH[ni][0], bH[ni][1]);
                }
        }

        if (pre) {   // store tile it+1 into the other stage (read at it-1, safe)
            const int nxt = cur ^ 1;
#pragma unroll
            for (int i = 0; i < 2; ++i) {
                int f = i * 512 + tid;
                uint4 h4, l4;
                split_tf32(pa[i].x, h4.x, l4.x); split_tf32(pa[i].y, h4.y, l4.y);
                split_tf32(pa[i].z, h4.z, l4.z); split_tf32(pa[i].w, h4.w, l4.w);
                int ao = (f >> 3) * AS_STRIDE + (f & 7) * 4;
                *(uint4*)&smem[OFF_AH(nxt) + ao] = h4;
                *(uint4*)&smem[OFF_AL(nxt) + ao] = l4;
                split_tf32(pb[i].x, h4.x, l4.x); split_tf32(pb[i].y, h4.y, l4.y);
                split_tf32(pb[i].z, h4.z, l4.z); split_tf32(pb[i].w, h4.w, l4.w);
                int bo = (f >> 5) * BS_STRIDE + (f & 31) * 4;
                *(uint4*)&smem[OFF_BH(nxt) + bo] = h4;
                *(uint4*)&smem[OFF_BL(nxt) + bo] = l4;
            }
        }

        // drain RZ accumulators into RN sums every 2 iters (64 k), as validated
        if ((it & 1) == 1) {
#pragma unroll
            for (int mi = 0; mi < 2; ++mi)
#pragma unroll
                for (int ni = 0; ni < 4; ++ni)
#pragma unroll
                    for (int c = 0; c < 4; ++c) {
                        sum[mi][ni][c] += acc[mi][ni][c];
                        acc[mi][ni][c] = 0.0f;
                    }
        }
    }

    // --- epilogue: extra feature cols (rank-1), bias, silu, store g_h ---
    const float step = stepp[0];
    float colc[4][2], w2r[4][2], w3r[4][2];
#pragma unroll
    for (int ni = 0; ni < 4; ++ni)
#pragma unroll
        for (int j = 0; j < 2; ++j) {
            int col = wn + ni * 8 + 2 * tg + j;
            colc[ni][j] = fmaf(step, W1[(size_t)D_SZ * H_SZ + col], b1[col]);
            w2r[ni][j]  = W1[(size_t)(D_SZ + 1) * H_SZ + col];
            w3r[ni][j]  = W1[(size_t)(D_SZ + 2) * H_SZ + col];
        }
#pragma unroll
    for (int mi = 0; mi < 2; ++mi) {
        int r0 = m0 + wm + mi * 16 + g;
        int r1 = r0 + 8;
        float hv0 = hn[r0], cv0 = conf[r0];
        float hv1 = hn[r1], cv1 = conf[r1];
#pragma unroll
        for (int ni = 0; ni < 4; ++ni) {
            int col0 = wn + ni * 8 + 2 * tg;
            float x00 = sum[mi][ni][0] + colc[ni][0] + hv0 * w2r[ni][0] + cv0 * w3r[ni][0];
            float x01 = sum[mi][ni][1] + colc[ni][1] + hv0 * w2r[ni][1] + cv0 * w3r[ni][1];
            float x10 = sum[mi][ni][2] + colc[ni][0] + hv1 * w2r[ni][0] + cv1 * w3r[ni][0];
            float x11 = sum[mi][ni][3] + colc[ni][1] + hv1 * w2r[ni][1] + cv1 * w3r[ni][1];
            float2 s0, s1;
            s0.x = x00 / (1.0f + expf(-x00));
            s0.y = x01 / (1.0f + expf(-x01));
            s1.x = x10 / (1.0f + expf(-x10));
            s1.y = x11 / (1.0f + expf(-x11));
            *(float2*)&g_h[(size_t)r0 * H_SZ + col0] = s0;
            *(float2*)&g_h[(size_t)r1 * H_SZ + col0] = s1;
        }
    }
}

// ---------------------------------------------------------------------------
// Kernel 2: logits = h @ W2 + b2; top-8 per row; softmax; scatter.
// One warp per row (unchanged — validated).
// ---------------------------------------------------------------------------
__global__ __launch_bounds__(256)
void router_kernel(const float* __restrict__ W2,
                   const float* __restrict__ b2,
                   float* __restrict__ out)
{
    __shared__ float Ws[H_SZ * E_SZ];
    __shared__ float b2s[E_SZ];

    const int tid = threadIdx.x;
    for (int i = tid; i < H_SZ * E_SZ; i += 256) Ws[i] = W2[i];
    if (tid < E_SZ) b2s[tid] = b2[tid];
    __syncthreads();

    const int lane = tid & 31;
    const int warp = tid >> 5;
    const int r = blockIdx.x * 8 + warp;

    float hreg[4];
#pragma unroll
    for (int q = 0; q < 4; ++q)
        hreg[q] = g_h[(size_t)r * H_SZ + q * 32 + lane];

    float acc0 = b2s[lane];
    float acc1 = b2s[lane + 32];
#pragma unroll
    for (int k = 0; k < H_SZ; ++k) {
        float hv = __shfl_sync(0xffffffffu, hreg[k >> 5], k & 31);
        acc0 = fmaf(hv, Ws[k * E_SZ + lane], acc0);
        acc1 = fmaf(hv, Ws[k * E_SZ + lane + 32], acc1);
    }

    float* out_w = out;
    float* out_l = out + (size_t)B_SZ * E_SZ;
    out_l[(size_t)r * E_SZ + lane]      = acc0;
    out_l[(size_t)r * E_SZ + lane + 32] = acc1;

    bool used0 = false, used1 = false;
    float tv[K_TOP];
    int   ti[K_TOP];
#pragma unroll
    for (int t = 0; t < K_TOP; ++t) {
        float mv = -3.402823466e38f;
        int   mi = 1 << 30;
        if (!used0) { mv = acc0; mi = lane; }
        if (!used1 && (acc1 > mv || (acc1 == mv && lane + 32 < mi))) {
            mv = acc1; mi = lane + 32;
        }
#pragma unroll
        for (int off = 16; off > 0; off >>= 1) {
            float ov = __shfl_xor_sync(0xffffffffu, mv, off);
            int   oi = __shfl_xor_sync(0xffffffffu, mi, off);
            if (ov > mv || (ov == mv && oi < mi)) { mv = ov; mi = oi; }
        }
        tv[t] = mv;
        ti[t] = mi;
        if (mi == lane)      used0 = true;
        if (mi == lane + 32) used1 = true;
    }

    float mx = tv[0];
    float s = 0.0f;
    float ev[K_TOP];
#pragma unroll
    for (int t = 0; t < K_TOP; ++t) { ev[t] = expf(tv[t] - mx); s += ev[t]; }
    float inv = 1.0f / s;

    float w0 = 0.0f, w1 = 0.0f;
#pragma unroll
    for (int t = 0; t < K_TOP; ++t) {
        float e = ev[t] * inv;
        if (ti[t] == lane)      w0 = e;
        if (ti[t] == lane + 32) w1 = e;
    }
    out_w[(size_t)r * E_SZ + lane]      = w0;
    out_w[(size_t)r * E_SZ + lane + 32] = w1;
}

// ---------------------------------------------------------------------------
extern "C" void kernel_launch(void* const* d_in, const int* in_sizes, int n_in,
                              void* d_out, int out_size) {
    const float* r_pooled    = (const float*)d_in[0];
    const float* step_frac   = (const float*)d_in[1];
    const float* hidden_norm = (const float*)d_in[2];
    const float* confidence  = (const float*)d_in[3];
    const float* W1          = (const float*)d_in[4];
    const float* b1          = (const float*)d_in[5];
    const float* W2          = (const float*)d_in[6];
    const float* b2          = (const float*)d_in[7];
    float* out = (float*)d_out;

    static int smem_set = 0;
    if (!smem_set) {
        cudaFuncSetAttribute(gemm1_3xtf32_kernel,
                             cudaFuncAttributeMaxDynamicSharedMemorySize,
                             SMEM_U32 * 4);
        smem_set = 1;
    }

    gemm1_3xtf32_kernel<<<B_SZ / 128, 512, SMEM_U32 * 4>>>(
        r_pooled, W1, b1, step_frac, hidden_norm, confidence);
    router_kernel<<<B_SZ / 8, 256>>>(W2, b2, out);
}

// round 9
// speedup vs baseline: 1.7150x; 1.0165x over previous
#include <cuda_runtime.h>
#include <math.h>
#include <stdint.h>

#define B_SZ 16384
#define D_SZ 4096
#define H_SZ 128
#define E_SZ 64
#define K_TOP 8

__device__ __forceinline__ uint32_t f2tf32(float x) {
    uint32_t r;
    asm("cvt.rna.tf32.f32 %0, %1;" : "=r"(r) : "f"(x));
    return r;
}
__device__ __forceinline__ void split_tf32(float x, uint32_t& hi, uint32_t& lo) {
    hi = f2tf32(x);
    lo = f2tf32(x - __uint_as_float(hi));
}

#define MMA_TF32(C, A0, A1, A2, A3, B0, B1)                                   \
    asm volatile(                                                             \
        "mma.sync.aligned.m16n8k8.row.col.f32.tf32.tf32.f32 "                 \
        "{%0,%1,%2,%3}, {%4,%5,%6,%7}, {%8,%9}, {%0,%1,%2,%3};"               \
        : "+f"(C[0]), "+f"(C[1]), "+f"(C[2]), "+f"(C[3])                      \
        : "r"(A0), "r"(A1), "r"(A2), "r"(A3), "r"(B0), "r"(B1))

// ---------------------------------------------------------------------------
// Fused kernel: h = silu(features @ W1 + b1)  [3xTF32 mma.sync, 2-stage pipe]
// then logits = h @ W2 + b2, top-8, softmax, scatter  [in-block epilogue].
// BM=128, BN=128(H), BK=32. 512 threads = 16 warps (4m x 4n), warp tile 32x32.
// ---------------------------------------------------------------------------
#define BK 32
#define AS_STRIDE 36   // bank(4r + 8ks + tg): frag loads conflict-free
#define BS_STRIDE 136  // bank(8tg + g): frag loads conflict-free

#define A_STG   (128 * AS_STRIDE)        // 4608 u32
#define B_STG   (BK * BS_STRIDE)         // 4352 u32
#define STG     (2 * A_STG + 2 * B_STG)  // 17920 u32 per stage
#define OFF_AH(s) ((s) * STG + 0)
#define OFF_AL(s) ((s) * STG + A_STG)
#define OFF_BH(s) ((s) * STG + 2 * A_STG)
#define OFF_BL(s) ((s) * STG + 2 * A_STG + B_STG)
#define SMEM_U32  (2 * STG)              // 35840 u32 = 143360 bytes

// epilogue overlays: hs (128 x HS_STRIDE f32) on stage 0, ws2 pairs on stage 1
#define HS_STRIDE 132                    // 128*132 = 16896 u32 <= STG

__global__ __launch_bounds__(512)
void fused_router_kernel(const float* __restrict__ A,     // (B, D)
                         const float* __restrict__ W1,    // (D+3, H)
                         const float* __restrict__ b1,    // (H)
                         const float* __restrict__ stepp, // (1)
                         const float* __restrict__ hn,    // (B)
                         const float* __restrict__ conf,  // (B)
                         const float* __restrict__ W2,    // (H, E)
                         const float* __restrict__ b2,    // (E)
                         float* __restrict__ out)
{
    extern __shared__ uint32_t smem[];

    const int tid  = threadIdx.x;
    const int lane = tid & 31;
    const int w    = tid >> 5;
    const int wm   = (w & 3) * 32;
    const int wn   = (w >> 2) * 32;
    const int g    = lane >> 2;
    const int tg   = lane & 3;
    const int m0   = blockIdx.x * 128;

    float acc[2][4][4];
    float sum[2][4][4];
#pragma unroll
    for (int mi = 0; mi < 2; ++mi)
#pragma unroll
        for (int ni = 0; ni < 4; ++ni)
#pragma unroll
            for (int c = 0; c < 4; ++c) { acc[mi][ni][c] = 0.0f; sum[mi][ni][c] = 0.0f; }

    float4 pa[2], pb[2];
#pragma unroll
    for (int i = 0; i < 2; ++i) {
        int f = i * 512 + tid;
        pa[i] = *(const float4*)&A[(size_t)(m0 + (f >> 3)) * D_SZ + (f & 7) * 4];
        pb[i] = *(const float4*)&W1[(size_t)(f >> 5) * H_SZ + (f & 31) * 4];
    }

    // prologue: fill stage 0
#pragma unroll
    for (int i = 0; i < 2; ++i) {
        int f = i * 512 + tid;
        uint4 h4, l4;
        split_tf32(pa[i].x, h4.x, l4.x); split_tf32(pa[i].y, h4.y, l4.y);
        split_tf32(pa[i].z, h4.z, l4.z); split_tf32(pa[i].w, h4.w, l4.w);
        int ao = (f >> 3) * AS_STRIDE + (f & 7) * 4;
        *(uint4*)&smem[OFF_AH(0) + ao] = h4;
        *(uint4*)&smem[OFF_AL(0) + ao] = l4;
        split_tf32(pb[i].x, h4.x, l4.x); split_tf32(pb[i].y, h4.y, l4.y);
        split_tf32(pb[i].z, h4.z, l4.z); split_tf32(pb[i].w, h4.w, l4.w);
        int bo = (f >> 5) * BS_STRIDE + (f & 31) * 4;
        *(uint4*)&smem[OFF_BH(0) + bo] = h4;
        *(uint4*)&smem[OFF_BL(0) + bo] = l4;
    }

    const int NIT = D_SZ / BK;   // 128
    for (int it = 0; it < NIT; ++it) {
        __syncthreads();
        const int cur = it & 1;
        const bool pre = (it + 1 < NIT);

        if (pre) {
            int k0 = (it + 1) * BK;
#pragma unroll
            for (int i = 0; i < 2; ++i) {
                int f = i * 512 + tid;
                pa[i] = *(const float4*)&A[(size_t)(m0 + (f >> 3)) * D_SZ + k0 + (f & 7) * 4];
                pb[i] = *(const float4*)&W1[(size_t)(k0 + (f >> 5)) * H_SZ + (f & 31) * 4];
            }
        }

        const uint32_t* AsH = &smem[OFF_AH(cur)];
        const uint32_t* AsL = &smem[OFF_AL(cur)];
        const uint32_t* BsH = &smem[OFF_BH(cur)];
        const uint32_t* BsL = &smem[OFF_BL(cur)];

#pragma unroll
        for (int ks = 0; ks < 4; ++ks) {
            uint32_t aH[2][4], aL[2][4], bH[4][2], bL[4][2];
#pragma unroll
            for (int mi = 0; mi < 2; ++mi) {
                int base = (wm + mi * 16 + g) * AS_STRIDE + ks * 8 + tg;
                aH[mi][0] = AsH[base];
                aH[mi][1] = AsH[base + 8 * AS_STRIDE];
                aH[mi][2] = AsH[base + 4];
                aH[mi][3] = AsH[base + 8 * AS_STRIDE + 4];
                aL[mi][0] = AsL[base];
                aL[mi][1] = AsL[base + 8 * AS_STRIDE];
                aL[mi][2] = AsL[base + 4];
                aL[mi][3] = AsL[base + 8 * AS_STRIDE + 4];
            }
#pragma unroll
            for (int ni = 0; ni < 4; ++ni) {
                int base = (ks * 8 + tg) * BS_STRIDE + wn + ni * 8 + g;
                bH[ni][0] = BsH[base];
                bH[ni][1] = BsH[base + 4 * BS_STRIDE];
                bL[ni][0] = BsL[base];
                bL[ni][1] = BsL[base + 4 * BS_STRIDE];
            }
#pragma unroll
            for (int mi = 0; mi < 2; ++mi)
#pragma unroll
                for (int ni = 0; ni < 4; ++ni) {
                    float* c = acc[mi][ni];
                    MMA_TF32(c, aL[mi][0], aL[mi][1], aL[mi][2], aL[mi][3],
                             bH[ni][0], bH[ni][1]);
                    MMA_TF32(c, aH[mi][0], aH[mi][1], aH[mi][2], aH[mi][3],
                             bL[ni][0], bL[ni][1]);
                    MMA_TF32(c, aH[mi][0], aH[mi][1], aH[mi][2], aH[mi][3],
                             bH[ni][0], bH[ni][1]);
                }
        }

        if (pre) {
            const int nxt = cur ^ 1;
#pragma unroll
            for (int i = 0; i < 2; ++i) {
                int f = i * 512 + tid;
                uint4 h4, l4;
                split_tf32(pa[i].x, h4.x, l4.x); split_tf32(pa[i].y, h4.y, l4.y);
                split_tf32(pa[i].z, h4.z, l4.z); split_tf32(pa[i].w, h4.w, l4.w);
                int ao = (f >> 3) * AS_STRIDE + (f & 7) * 4;
                *(uint4*)&smem[OFF_AH(nxt) + ao] = h4;
                *(uint4*)&smem[OFF_AL(nxt) + ao] = l4;
                split_tf32(pb[i].x, h4.x, l4.x); split_tf32(pb[i].y, h4.y, l4.y);
                split_tf32(pb[i].z, h4.z, l4.z); split_tf32(pb[i].w, h4.w, l4.w);
                int bo = (f >> 5) * BS_STRIDE + (f & 31) * 4;
                *(uint4*)&smem[OFF_BH(nxt) + bo] = h4;
                *(uint4*)&smem[OFF_BL(nxt) + bo] = l4;
            }
        }

        if ((it & 1) == 1) {
#pragma unroll
            for (int mi = 0; mi < 2; ++mi)
#pragma unroll
                for (int ni = 0; ni < 4; ++ni)
#pragma unroll
                    for (int c = 0; c < 4; ++c) {
                        sum[mi][ni][c] += acc[mi][ni][c];
                        acc[mi][ni][c] = 0.0f;
                    }
        }
    }

    // ---- epilogue stage A: rank-1 terms, bias, silu -> hs in smem (stage 0) ----
    // Safe without a sync: all warps have passed it=127's barrier, so stage 0
    // (last read at it=126) is no longer referenced; hs overlays stage 0 only.
    float* hs = (float*)smem;                       // [128][HS_STRIDE]
    {
        const float step = stepp[0];
        float colc[4][2], w2r[4][2], w3r[4][2];
#pragma unroll
        for (int ni = 0; ni < 4; ++ni)
#pragma unroll
            for (int j = 0; j < 2; ++j) {
                int col = wn + ni * 8 + 2 * tg + j;
                colc[ni][j] = fmaf(step, W1[(size_t)D_SZ * H_SZ + col], b1[col]);
                w2r[ni][j]  = W1[(size_t)(D_SZ + 1) * H_SZ + col];
                w3r[ni][j]  = W1[(size_t)(D_SZ + 2) * H_SZ + col];
            }
#pragma unroll
        for (int mi = 0; mi < 2; ++mi) {
            int lr0 = wm + mi * 16 + g;
            int lr1 = lr0 + 8;
            float hv0 = hn[m0 + lr0], cv0 = conf[m0 + lr0];
            float hv1 = hn[m0 + lr1], cv1 = conf[m0 + lr1];
#pragma unroll
            for (int ni = 0; ni < 4; ++ni) {
                int col0 = wn + ni * 8 + 2 * tg;
                float x00 = sum[mi][ni][0] + colc[ni][0] + hv0 * w2r[ni][0] + cv0 * w3r[ni][0];
                float x01 = sum[mi][ni][1] + colc[ni][1] + hv0 * w2r[ni][1] + cv0 * w3r[ni][1];
                float x10 = sum[mi][ni][2] + colc[ni][0] + hv1 * w2r[ni][0] + cv1 * w3r[ni][0];
                float x11 = sum[mi][ni][3] + colc[ni][1] + hv1 * w2r[ni][1] + cv1 * w3r[ni][1];
                float2 s0, s1;
                s0.x = x00 / (1.0f + expf(-x00));
                s0.y = x01 / (1.0f + expf(-x01));
                s1.x = x10 / (1.0f + expf(-x10));
                s1.y = x11 / (1.0f + expf(-x11));
                *(float2*)&hs[lr0 * HS_STRIDE + col0] = s0;
                *(float2*)&hs[lr1 * HS_STRIDE + col0] = s1;
            }
        }
    }
    __syncthreads();   // hs complete; stage 1 no longer needed by anyone

    // ---- epilogue stage B: load W2 pair-permuted into stage-1 smem ----
    float2* ws2 = (float2*)&smem[STG];              // [H_SZ][32] pairs (e, e+32)
    for (int i = tid; i < H_SZ * 32; i += 512) {
        int k = i >> 5, j = i & 31;
        ws2[i] = make_float2(W2[k * E_SZ + j], W2[k * E_SZ + j + 32]);
    }
    __syncthreads();

    // ---- epilogue stage C: per-warp GEMV + top-8 + softmax for 8 rows ----
    {
        const float bz0 = b2[lane];
        const float bz1 = b2[lane + 32];
        float acc0[8], acc1[8];
#pragma unroll
        for (int rr = 0; rr < 8; ++rr) { acc0[rr] = bz0; acc1[rr] = bz1; }

        const float* hrow = &hs[(w * 8) * HS_STRIDE];
        for (int k = 0; k < H_SZ; ++k) {
            float2 wv = ws2[k * 32 + lane];
#pragma unroll
            for (int rr = 0; rr < 8; ++rr) {
                float hv = hrow[rr * HS_STRIDE + k];    // LDS broadcast
                acc0[rr] = fmaf(hv, wv.x, acc0[rr]);
                acc1[rr] = fmaf(hv, wv.y, acc1[rr]);
            }
        }

        float* out_w = out;
        float* out_l = out + (size_t)B_SZ * E_SZ;
#pragma unroll
        for (int rr = 0; rr < 8; ++rr) {
            const int r = m0 + w * 8 + rr;
            const float a0 = acc0[rr], a1 = acc1[rr];
            out_l[(size_t)r * E_SZ + lane]      = a0;
            out_l[(size_t)r * E_SZ + lane + 32] = a1;

            bool used0 = false, used1 = false;
            float tv[K_TOP];
            int   ti[K_TOP];
#pragma unroll
            for (int t = 0; t < K_TOP; ++t) {
                float mv = -3.402823466e38f;
                int   mi = 1 << 30;
                if (!used0) { mv = a0; mi = lane; }
                if (!used1 && (a1 > mv || (a1 == mv && lane + 32 < mi))) {
                    mv = a1; mi = lane + 32;
                }
#pragma unroll
                for (int off = 16; off > 0; off >>= 1) {
                    float ov = __shfl_xor_sync(0xffffffffu, mv, off);
                    int   oi = __shfl_xor_sync(0xffffffffu, mi, off);
                    if (ov > mv || (ov == mv && oi < mi)) { mv = ov; mi = oi; }
                }
                tv[t] = mv;
                ti[t] = mi;
                if (mi == lane)      used0 = true;
                if (mi == lane + 32) used1 = true;
            }

            float mx = tv[0];
            float s = 0.0f;
            float ev[K_TOP];
#pragma unroll
            for (int t = 0; t < K_TOP; ++t) { ev[t] = expf(tv[t] - mx); s += ev[t]; }
            float inv = 1.0f / s;

            float w0 = 0.0f, w1 = 0.0f;
#pragma unroll
            for (int t = 0; t < K_TOP; ++t) {
                float e = ev[t] * inv;
                if (ti[t] == lane)      w0 = e;
                if (ti[t] == lane + 32) w1 = e;
            }
            out_w[(size_t)r * E_SZ + lane]      = w0;
            out_w[(size_t)r * E_SZ + lane + 32] = w1;
        }
    }
}

// ---------------------------------------------------------------------------
extern "C" void kernel_launch(void* const* d_in, const int* in_sizes, int n_in,
                              void* d_out, int out_size) {
    const float* r_pooled    = (const float*)d_in[0];
    const float* step_frac   = (const float*)d_in[1];
    const float* hidden_norm = (const float*)d_in[2];
    const float* confidence  = (const float*)d_in[3];
    const float* W1          = (const float*)d_in[4];
    const float* b1          = (const float*)d_in[5];
    const float* W2          = (const float*)d_in[6];
    const float* b2          = (const float*)d_in[7];
    float* out = (float*)d_out;

    static int smem_set = 0;
    if (!smem_set) {
        cudaFuncSetAttribute(fused_router_kernel,
                             cudaFuncAttributeMaxDynamicSharedMemorySize,
                             SMEM_U32 * 4);
        smem_set = 1;
    }

    fused_router_kernel<<<B_SZ / 128, 512, SMEM_U32 * 4>>>(
        r_pooled, W1, b1, step_frac, hidden_norm, confidence, W2, b2, out);
}